// round 16
// baseline (speedup 1.0000x reference)
#include <cuda_runtime.h>
#include <cuda_fp16.h>
#include <cstdint>

#define BB 16
#define NN 4096

// ---------------- scratch (device globals; no dynamic allocation) ----------
// g_adjh tiled layout: [b][mtile(32)][kchunk(64)] blocks of 16KB
//   block = 128 rows(m) x 64 k fp16, SW128-swizzled: off = r*128 + ((c^(r&7))<<4) + (k&7)*2
// g_z*  tiled layout: [b][kchunk(64)] blocks of 8KB, same swizzle (64 rows d)
__device__ float g_dis[BB * NN];                            // 256 KB
__device__ __align__(128) __half g_adjh[(size_t)BB * NN * NN];   // 512 MB
__device__ __align__(128) __half g_z1[(size_t)BB * 64 * NN];     // 8 MB
__device__ __align__(128) __half g_z2[(size_t)BB * 64 * NN];     // 8 MB
__device__ float g_pool[BB * 32 * 128];                     // pool partials

// ---------------- small PTX helpers ----------------------------------------
__device__ __forceinline__ void ldm4(uint32_t& r0, uint32_t& r1, uint32_t& r2,
                                     uint32_t& r3, uint32_t a) {
    asm volatile("ldmatrix.sync.aligned.m8n8.x4.shared.b16 {%0,%1,%2,%3}, [%4];"
                 : "=r"(r0), "=r"(r1), "=r"(r2), "=r"(r3) : "r"(a));
}
__device__ __forceinline__ void mma16816(float* d, const uint32_t* a, const uint32_t* b) {
    asm volatile(
        "mma.sync.aligned.m16n8k16.row.col.f32.f16.f16.f32 "
        "{%0,%1,%2,%3},{%4,%5,%6,%7},{%8,%9},{%0,%1,%2,%3};"
        : "+f"(d[0]), "+f"(d[1]), "+f"(d[2]), "+f"(d[3])
        : "r"(a[0]), "r"(a[1]), "r"(a[2]), "r"(a[3]), "r"(b[0]), "r"(b[1]));
}
__device__ __forceinline__ void mbar_init(uint32_t a, uint32_t cnt) {
    asm volatile("mbarrier.init.shared.b64 [%0], %1;" :: "r"(a), "r"(cnt) : "memory");
}
__device__ __forceinline__ void mbar_expect(uint32_t a, uint32_t bytes) {
    asm volatile("mbarrier.arrive.expect_tx.shared.b64 _, [%0], %1;"
                 :: "r"(a), "r"(bytes) : "memory");
}
__device__ __forceinline__ void bulk_g2s(uint32_t dst, const void* src,
                                         uint32_t bytes, uint32_t mbar) {
    asm volatile("cp.async.bulk.shared::cluster.global.mbarrier::complete_tx::bytes "
                 "[%0], [%1], %2, [%3];"
                 :: "r"(dst), "l"(src), "r"(bytes), "r"(mbar) : "memory");
}
__device__ __forceinline__ void mbar_wait(uint32_t a, uint32_t parity) {
    asm volatile(
        "{\n\t.reg .pred P;\n"
        "WL%=:\n\t"
        "mbarrier.try_wait.parity.acquire.cta.shared::cta.b64 P, [%0], %1;\n\t"
        "@P bra WD%=;\n\t"
        "bra WL%=;\n"
        "WD%=:\n\t}"
        :: "r"(a), "r"(parity) : "memory");
}

// load W^T (64x64) into swizzled fp16 smem tile: ws[d][k] = W[k][d]
__device__ __forceinline__ void load_wT(const float* __restrict__ W, char* wsPtr, int tid) {
    for (int idx = tid; idx < 4096; idx += 256) {
        int d = idx & 63, k = idx >> 6;
        int chunk = k >> 3;
        int off = d * 128 + ((chunk ^ (d & 7)) << 4) + (k & 7) * 2;
        *(__half*)(wsPtr + off) = __float2half(W[k * 64 + d]);
    }
}

// mini MMA: [128x64 fp16 smem tile @xsA] x [64x64 W^T @wsA] -> zs[d][m] (pad 136)
__device__ __forceinline__ void mini_mma_store(uint32_t xsA, uint32_t wsA,
                                               __half* zs,
                                               int wm, int wn, int lane) {
    float acc[2][4][4];
#pragma unroll
    for (int mt = 0; mt < 2; mt++)
#pragma unroll
        for (int nt = 0; nt < 4; nt++)
#pragma unroll
            for (int c = 0; c < 4; c++) acc[mt][nt][c] = 0.f;

#pragma unroll
    for (int kt = 0; kt < 4; kt++) {
        uint32_t a[2][4], bb[4][2];
        int chunk = kt * 2 + (lane >> 4);
#pragma unroll
        for (int mt = 0; mt < 2; mt++) {
            int row = wm * 32 + mt * 16 + (lane & 15);
            ldm4(a[mt][0], a[mt][1], a[mt][2], a[mt][3],
                 xsA + row * 128 + ((chunk ^ (row & 7)) << 4));
        }
#pragma unroll
        for (int pr = 0; pr < 2; pr++) {
            int rn = wn * 32 + pr * 16 + (lane & 15);
            uint32_t r0, r1, r2, r3;
            ldm4(r0, r1, r2, r3, wsA + rn * 128 + ((chunk ^ (rn & 7)) << 4));
            bb[pr * 2][0] = r0; bb[pr * 2 + 1][0] = r1;
            bb[pr * 2][1] = r2; bb[pr * 2 + 1][1] = r3;
        }
#pragma unroll
        for (int mt = 0; mt < 2; mt++)
#pragma unroll
            for (int nt = 0; nt < 4; nt++) mma16816(acc[mt][nt], a[mt], bb[nt]);
    }
    int g = lane >> 2, t4 = lane & 3;
#pragma unroll
    for (int mt = 0; mt < 2; mt++)
#pragma unroll
        for (int nt = 0; nt < 4; nt++)
#pragma unroll
            for (int h2 = 0; h2 < 2; h2++) {
                int row = wm * 32 + mt * 16 + g + h2 * 8;
                int col = wn * 32 + nt * 8 + t4 * 2;
                zs[(size_t)col * 136 + row]       = __float2half(acc[mt][nt][h2 * 2]);
                zs[(size_t)(col + 1) * 136 + row] = __float2half(acc[mt][nt][h2 * 2 + 1]);
            }
}

// z tiled-layout store: v packs (m, m+1) halves for dim d
__device__ __forceinline__ void store_z_tiled(__half* zbase, int b, int d, int m,
                                              uint32_t v) {
    int kc = m >> 6, ml = m & 63, c = ml >> 3;
    size_t off = ((size_t)(b * 64 + kc)) * 8192 + d * 128 + ((c ^ (d & 7)) << 4) + (ml & 7) * 2;
    *reinterpret_cast<uint32_t*>(reinterpret_cast<char*>(zbase) + off) = v;
}

// ---------------- 1) deg + dis + fp16 tiled/swizzled conversion (per batch) -
__global__ void conv_deg(const float* __restrict__ adj, int b) {
    size_t row = (size_t)b * NN + blockIdx.x;
    int t = threadIdx.x;
    const float4* p = reinterpret_cast<const float4*>(adj + row * NN);
    float4 v[8];
#pragma unroll
    for (int i = 0; i < 8; i++) v[i] = __ldcs(p + t + i * 128);
    float s = 0.f;
#pragma unroll
    for (int i = 0; i < 8; i++) s += (v[i].x + v[i].y) + (v[i].z + v[i].w);
#pragma unroll
    for (int o = 16; o; o >>= 1) s += __shfl_xor_sync(0xffffffffu, s, o);
    __shared__ float ws[4];
    __shared__ float sdis;
    if ((t & 31) == 0) ws[t >> 5] = s;
    __syncthreads();
    if (t == 0) {
        float tot = ws[0] + ws[1] + ws[2] + ws[3];
        float dis = rsqrtf(fmaxf(tot, 1.0f));
        g_dis[row] = dis;
        sdis = dis;
    }
    __syncthreads();
    float d = sdis;
    int m = blockIdx.x;
    int mt = m >> 7, r = m & 127;
    char* blockBase = reinterpret_cast<char*>(g_adjh) +
                      ((size_t)(b * 32 + mt)) * 64 * 16384;
#pragma unroll
    for (int i = 0; i < 8; i++) {
        __half2 lo = __floats2half2_rn(v[i].x * d, v[i].y * d);
        __half2 hi = __floats2half2_rn(v[i].z * d, v[i].w * d);
        uint2 o;
        o.x = *reinterpret_cast<uint32_t*>(&lo);
        o.y = *reinterpret_cast<uint32_t*>(&hi);
        int k0 = 4 * (t + i * 128);
        int kc = k0 >> 6, c = (k0 & 63) >> 3;
        size_t off = (size_t)kc * 16384 + r * 128 + ((c ^ (r & 7)) << 4) + (k0 & 7) * 2;
        __stcs(reinterpret_cast<uint2*>(blockBase + off), o);
    }
}

// ---------------- 2) proj1: z1 = dis*(x @ W1), fp16, tiled layout (per batch)
__global__ void __launch_bounds__(256) proj1_kernel(
    const int* __restrict__ ntypes, const int* __restrict__ nlabels,
    const float* __restrict__ te, const float* __restrict__ le,
    const float* __restrict__ W1, int b) {
    __shared__ __align__(16) char sm[41984];   // xs 16K | ws 8K | zs 17408
    int tid = threadIdx.x;
    int m0 = blockIdx.x * 128;
    load_wT(W1, sm + 16384, tid);

    int node_l = tid >> 1, half = tid & 1;
    size_t node = (size_t)b * NN + m0 + node_l;
    const float* src = half ? (le + nlabels[node] * 32) : (te + ntypes[node] * 32);
    float dv = g_dis[node];
#pragma unroll
    for (int j = 0; j < 8; j++) {
        float4 v = reinterpret_cast<const float4*>(src)[j];
        __half2 p0 = __floats2half2_rn(v.x * dv, v.y * dv);
        __half2 p1 = __floats2half2_rn(v.z * dv, v.w * dv);
        int col = half * 32 + j * 4;
        int chunk = col >> 3;
        int off = node_l * 128 + ((chunk ^ (node_l & 7)) << 4) + (col & 7) * 2;
        uint2 u;
        u.x = *reinterpret_cast<uint32_t*>(&p0);
        u.y = *reinterpret_cast<uint32_t*>(&p1);
        *reinterpret_cast<uint2*>(sm + off) = u;
    }
    __syncthreads();

    int warp = tid >> 5, lane = tid & 31, wm = warp >> 1, wn = warp & 1;
    uint32_t sA = (uint32_t)__cvta_generic_to_shared(sm);
    __half* zs = reinterpret_cast<__half*>(sm + 24576);
    mini_mma_store(sA, sA + 16384, zs, wm, wn, lane);
    __syncthreads();

    for (int idx = tid; idx < 4096; idx += 256) {
        int d = idx >> 6, cw = idx & 63;
        uint32_t v = *reinterpret_cast<uint32_t*>(zs + d * 136 + cw * 2);
        store_z_tiled(g_z1, b, d, m0 + cw * 2, v);
    }
}

// ---------------- 3) main GEMM (R9 verbatim, per batch) ---------------------
// mode 1: acc = adjh @ z1^T ; h = relu(acc + b1); z2 = dis[m]*(h @ W2) -> g_z2
// mode 2: acc = adjh @ z2^T ; h = relu(acc + b2); pool partials -> g_pool
// smem: A stages [2][16KB] @0 | B stages [2][8KB] @32768 ; total 49152 dynamic
__global__ void __launch_bounds__(256, 4) gcn_gemm(
    const float* __restrict__ bias, const float* __restrict__ Wnext,
    int mode, int b) {
    extern __shared__ char sm[];
    __shared__ __align__(8) uint64_t mb_full[2];
    int tid = threadIdx.x, m0 = blockIdx.x * 128;
    uint32_t sA = (uint32_t)__cvta_generic_to_shared(sm);
    uint32_t sB = sA + 32768;
    uint32_t mbF = (uint32_t)__cvta_generic_to_shared(mb_full);
    int warp = tid >> 5, lane = tid & 31, wm = warp >> 1, wn = warp & 1;
    int g = lane >> 2, t4 = lane & 3;

    const char* aTile = reinterpret_cast<const char*>(g_adjh) +
                        ((size_t)(b * 32 + blockIdx.x)) * 64 * 16384;
    const char* zTile = reinterpret_cast<const char*>(mode == 1 ? g_z1 : g_z2) +
                        (size_t)b * 64 * 8192;

    if (tid == 0) {
        mbar_init(mbF + 0, 1);
        mbar_init(mbF + 8, 1);
    }
    __syncthreads();
    if (tid == 0) {
#pragma unroll
        for (int s = 0; s < 2; s++) {
            mbar_expect(mbF + s * 8, 24576);
            bulk_g2s(sA + s * 16384, aTile + (size_t)s * 16384, 16384, mbF + s * 8);
            bulk_g2s(sB + s * 8192,  zTile + (size_t)s * 8192,  8192,  mbF + s * 8);
        }
    }

    float acc[2][4][4];
#pragma unroll
    for (int mt = 0; mt < 2; mt++)
#pragma unroll
        for (int nt = 0; nt < 4; nt++)
#pragma unroll
            for (int c = 0; c < 4; c++) acc[mt][nt][c] = 0.f;

    for (int kb = 0; kb < 64; kb++) {
        int buf = kb & 1;
        uint32_t par = (kb >> 1) & 1;
        mbar_wait(mbF + buf * 8, par);
        uint32_t Ab = sA + buf * 16384, Bb = sB + buf * 8192;
#pragma unroll
        for (int kt = 0; kt < 4; kt++) {
            uint32_t a[2][4], bb[4][2];
            int chunk = kt * 2 + (lane >> 4);
#pragma unroll
            for (int mt = 0; mt < 2; mt++) {
                int row = wm * 32 + mt * 16 + (lane & 15);
                ldm4(a[mt][0], a[mt][1], a[mt][2], a[mt][3],
                     Ab + row * 128 + ((chunk ^ (row & 7)) << 4));
            }
#pragma unroll
            for (int pr = 0; pr < 2; pr++) {
                int rn = wn * 32 + pr * 16 + (lane & 15);
                uint32_t r0, r1, r2, r3;
                ldm4(r0, r1, r2, r3, Bb + rn * 128 + ((chunk ^ (rn & 7)) << 4));
                bb[pr * 2][0] = r0; bb[pr * 2 + 1][0] = r1;
                bb[pr * 2][1] = r2; bb[pr * 2 + 1][1] = r3;
            }
#pragma unroll
            for (int mt = 0; mt < 2; mt++)
#pragma unroll
                for (int nt = 0; nt < 4; nt++) mma16816(acc[mt][nt], a[mt], bb[nt]);
        }
        __syncthreads();
        if (tid == 0 && kb + 2 < 64) {
            mbar_expect(mbF + buf * 8, 24576);
            bulk_g2s(sA + buf * 16384, aTile + (size_t)(kb + 2) * 16384, 16384, mbF + buf * 8);
            bulk_g2s(sB + buf * 8192,  zTile + (size_t)(kb + 2) * 8192,  8192,  mbF + buf * 8);
        }
    }

    if (mode == 1) {
        // W^T into smem tail + stage h' fp16 tile at sm[0]; zs at sm+16384
        load_wT(Wnext, sm + 40960, tid);
#pragma unroll
        for (int mt = 0; mt < 2; mt++)
#pragma unroll
            for (int h2 = 0; h2 < 2; h2++) {
                int row = wm * 32 + mt * 16 + g + h2 * 8;
                float dv = g_dis[b * NN + m0 + row];
#pragma unroll
                for (int nt = 0; nt < 4; nt++) {
                    int col = wn * 32 + nt * 8 + t4 * 2;
                    float v0 = fmaxf(acc[mt][nt][h2 * 2]     + bias[col],     0.f) * dv;
                    float v1 = fmaxf(acc[mt][nt][h2 * 2 + 1] + bias[col + 1], 0.f) * dv;
                    int chunk = col >> 3;
                    int off = row * 128 + ((chunk ^ (row & 7)) << 4) + (col & 7) * 2;
                    __half2 p = __floats2half2_rn(v0, v1);
                    *reinterpret_cast<uint32_t*>(sm + off) = *reinterpret_cast<uint32_t*>(&p);
                }
            }
        __syncthreads();
        __half* zs = reinterpret_cast<__half*>(sm + 16384);
        mini_mma_store(sA, sA + 40960, zs, wm, wn, lane);
        __syncthreads();
        for (int idx = tid; idx < 4096; idx += 256) {
            int d = idx >> 6, cw = idx & 63;
            uint32_t v = *reinterpret_cast<uint32_t*>(zs + d * 136 + cw * 2);
            store_z_tiled(g_z2, b, d, m0 + cw * 2, v);
        }
    } else {
        // stage h = relu(acc + b2) fp32, then pool partials
        float* hs = reinterpret_cast<float*>(sm);
#pragma unroll
        for (int mt = 0; mt < 2; mt++)
#pragma unroll
            for (int h2 = 0; h2 < 2; h2++) {
                int row = wm * 32 + mt * 16 + g + h2 * 8;
#pragma unroll
                for (int nt = 0; nt < 4; nt++) {
                    int col = wn * 32 + nt * 8 + t4 * 2;
                    hs[row * 65 + col]     = fmaxf(acc[mt][nt][h2 * 2]     + bias[col],     0.f);
                    hs[row * 65 + col + 1] = fmaxf(acc[mt][nt][h2 * 2 + 1] + bias[col + 1], 0.f);
                }
            }
        __syncthreads();
        float* red = reinterpret_cast<float*>(sm + 33792);
        int d = tid & 63, part = tid >> 6;
        float s = 0.f, mx = -1e30f;
#pragma unroll 4
        for (int r = part * 32; r < part * 32 + 32; r++) {
            float v = hs[r * 65 + d];
            s += v; mx = fmaxf(mx, v);
        }
        red[tid] = s; red[256 + tid] = mx;
        __syncthreads();
        if (tid < 64) {
            float S = red[tid] + red[tid + 64] + red[tid + 128] + red[tid + 192];
            float M = fmaxf(fmaxf(red[256 + tid], red[256 + tid + 64]),
                            fmaxf(red[256 + tid + 128], red[256 + tid + 192]));
            g_pool[((b * 32 + blockIdx.x) << 7) + tid]      = S;
            g_pool[((b * 32 + blockIdx.x) << 7) + 64 + tid] = M;
        }
    }
}

// ---------------- 4) final combine + readout --------------------------------
__global__ void final_kernel(const float* __restrict__ Wr,
                             const float* __restrict__ br,
                             float* __restrict__ out) {
    int b = blockIdx.x, t = threadIdx.x;
    __shared__ float pooled[128];
    if (t < 64) {
        float s = 0.f;
        for (int c = 0; c < 32; c++) s += g_pool[((b * 32 + c) << 7) + t];
        pooled[t] = s * (1.0f / 4096.0f);
    } else {
        float m = -1e30f;
        for (int c = 0; c < 32; c++) m = fmaxf(m, g_pool[((b * 32 + c) << 7) + (t - 64) + 64]);
        pooled[t] = m;
    }
    __syncthreads();
    if (t < 64) {
        float acc = br[t];
#pragma unroll
        for (int j = 0; j < 128; j++) acc += pooled[j] * Wr[t * 128 + j];
        out[b * 64 + t] = acc;
    }
}

// ---------------- launch: two-stream pipelined schedule ----------------------
extern "C" void kernel_launch(void* const* d_in, const int* in_sizes, int n_in,
                              void* d_out, int out_size) {
    const int*   node_types  = (const int*)  d_in[0];
    const int*   node_labels = (const int*)  d_in[1];
    const float* adj         = (const float*)d_in[2];
    const float* type_emb    = (const float*)d_in[3];
    const float* label_emb   = (const float*)d_in[4];
    const float* W1          = (const float*)d_in[5];
    const float* b1          = (const float*)d_in[6];
    const float* W2          = (const float*)d_in[7];
    const float* b2          = (const float*)d_in[8];
    const float* Wr          = (const float*)d_in[9];
    const float* br          = (const float*)d_in[10];
    float* out = (float*)d_out;

    cudaFuncSetAttribute(gcn_gemm, cudaFuncAttributeMaxDynamicSharedMemorySize, 49152);

    // Fresh stream/events each call (no static guards; host objects only, no
    // device allocation). kernel_launch runs only for correctness + capture.
    cudaStream_t s2;
    cudaStreamCreateWithFlags(&s2, cudaStreamNonBlocking);
    cudaEvent_t evConv[BB], evJoin;
    for (int b = 0; b < BB; b++)
        cudaEventCreateWithFlags(&evConv[b], cudaEventDisableTiming);
    cudaEventCreateWithFlags(&evJoin, cudaEventDisableTiming);

    // Stream A (capture/default): per-batch conv, record readiness events.
    for (int b = 0; b < BB; b++) {
        conv_deg<<<NN, 128>>>(adj, b);
        cudaEventRecord(evConv[b], 0);
    }
    // Stream B: per-batch proj1 -> gemm1 -> gemm2, gated on conv(b).
    for (int b = 0; b < BB; b++) {
        cudaStreamWaitEvent(s2, evConv[b], 0);
        proj1_kernel<<<NN / 128, 256, 0, s2>>>(node_types, node_labels,
                                               type_emb, label_emb, W1, b);
        gcn_gemm<<<32, 256, 49152, s2>>>(b1, W2, 1, b);
        gcn_gemm<<<32, 256, 49152, s2>>>(b2, nullptr, 2, b);
    }
    cudaEventRecord(evJoin, s2);
    cudaStreamWaitEvent(0, evJoin, 0);
    final_kernel<<<BB, 128>>>(Wr, br, out);
    // streams/events intentionally not destroyed (graph may reference them;
    // leaked host objects only, bounded by the 2 calls the harness makes)
}

// round 17
// speedup vs baseline: 3.5901x; 3.5901x over previous
#include <cuda_runtime.h>
#include <cuda_fp16.h>
#include <cstdint>

#define BB 16
#define NN 4096

// ---------------- scratch (device globals; no dynamic allocation) ----------
// g_adjh tiled layout: [b][mtile(32)][kchunk(64)] blocks of 16KB
//   block = 128 rows(m) x 64 k fp16, SW128-swizzled: off = r*128 + ((c^(r&7))<<4) + (k&7)*2
// g_z*  tiled layout: [b][kchunk(64)] blocks of 8KB, same swizzle (64 rows d)
__device__ float g_dis[BB * NN];                            // 256 KB
__device__ __align__(128) __half g_adjh[(size_t)BB * NN * NN];   // 512 MB
__device__ __align__(128) __half g_z1[(size_t)BB * 64 * NN];     // 8 MB
__device__ __align__(128) __half g_z2[(size_t)BB * 64 * NN];     // 8 MB
__device__ float g_pool[BB * 32 * 128];                     // pool partials

// ---------------- small PTX helpers ----------------------------------------
__device__ __forceinline__ void ldm4(uint32_t& r0, uint32_t& r1, uint32_t& r2,
                                     uint32_t& r3, uint32_t a) {
    asm volatile("ldmatrix.sync.aligned.m8n8.x4.shared.b16 {%0,%1,%2,%3}, [%4];"
                 : "=r"(r0), "=r"(r1), "=r"(r2), "=r"(r3) : "r"(a));
}
__device__ __forceinline__ void mma16816(float* d, const uint32_t* a, const uint32_t* b) {
    asm volatile(
        "mma.sync.aligned.m16n8k16.row.col.f32.f16.f16.f32 "
        "{%0,%1,%2,%3},{%4,%5,%6,%7},{%8,%9},{%0,%1,%2,%3};"
        : "+f"(d[0]), "+f"(d[1]), "+f"(d[2]), "+f"(d[3])
        : "r"(a[0]), "r"(a[1]), "r"(a[2]), "r"(a[3]), "r"(b[0]), "r"(b[1]));
}
__device__ __forceinline__ void mbar_init(uint32_t a, uint32_t cnt) {
    asm volatile("mbarrier.init.shared.b64 [%0], %1;" :: "r"(a), "r"(cnt) : "memory");
}
__device__ __forceinline__ void mbar_expect(uint32_t a, uint32_t bytes) {
    asm volatile("mbarrier.arrive.expect_tx.shared.b64 _, [%0], %1;"
                 :: "r"(a), "r"(bytes) : "memory");
}
// plain bulk copy (B operand: keep default / L2-resident)
__device__ __forceinline__ void bulk_g2s(uint32_t dst, const void* src,
                                         uint32_t bytes, uint32_t mbar) {
    asm volatile("cp.async.bulk.shared::cluster.global.mbarrier::complete_tx::bytes "
                 "[%0], [%1], %2, [%3];"
                 :: "r"(dst), "l"(src), "r"(bytes), "r"(mbar) : "memory");
}
// streaming bulk copy (A operand: evict_first so B stays L2-hot)
__device__ __forceinline__ void bulk_g2s_stream(uint32_t dst, const void* src,
                                                uint32_t bytes, uint32_t mbar) {
    asm volatile(
        "{\n\t.reg .b64 pol;\n\t"
        "createpolicy.fractional.L2::evict_first.b64 pol, 1.0;\n\t"
        "cp.async.bulk.shared::cluster.global.mbarrier::complete_tx::bytes.L2::cache_hint "
        "[%0], [%1], %2, [%3], pol;\n\t}"
        :: "r"(dst), "l"(src), "r"(bytes), "r"(mbar) : "memory");
}
__device__ __forceinline__ void mbar_wait(uint32_t a, uint32_t parity) {
    asm volatile(
        "{\n\t.reg .pred P;\n"
        "WL%=:\n\t"
        "mbarrier.try_wait.parity.acquire.cta.shared::cta.b64 P, [%0], %1;\n\t"
        "@P bra WD%=;\n\t"
        "bra WL%=;\n"
        "WD%=:\n\t}"
        :: "r"(a), "r"(parity) : "memory");
}

// load W^T (64x64) into swizzled fp16 smem tile: ws[d][k] = W[k][d]
__device__ __forceinline__ void load_wT(const float* __restrict__ W, char* wsPtr, int tid) {
    for (int idx = tid; idx < 4096; idx += 256) {
        int d = idx & 63, k = idx >> 6;
        int chunk = k >> 3;
        int off = d * 128 + ((chunk ^ (d & 7)) << 4) + (k & 7) * 2;
        *(__half*)(wsPtr + off) = __float2half(W[k * 64 + d]);
    }
}

// mini MMA: [128x64 fp16 smem tile @xsA] x [64x64 W^T @wsA] -> zs[d][m] (pad 136)
__device__ __forceinline__ void mini_mma_store(uint32_t xsA, uint32_t wsA,
                                               __half* zs,
                                               int wm, int wn, int lane) {
    float acc[2][4][4];
#pragma unroll
    for (int mt = 0; mt < 2; mt++)
#pragma unroll
        for (int nt = 0; nt < 4; nt++)
#pragma unroll
            for (int c = 0; c < 4; c++) acc[mt][nt][c] = 0.f;

#pragma unroll
    for (int kt = 0; kt < 4; kt++) {
        uint32_t a[2][4], bb[4][2];
        int chunk = kt * 2 + (lane >> 4);
#pragma unroll
        for (int mt = 0; mt < 2; mt++) {
            int row = wm * 32 + mt * 16 + (lane & 15);
            ldm4(a[mt][0], a[mt][1], a[mt][2], a[mt][3],
                 xsA + row * 128 + ((chunk ^ (row & 7)) << 4));
        }
#pragma unroll
        for (int pr = 0; pr < 2; pr++) {
            int rn = wn * 32 + pr * 16 + (lane & 15);
            uint32_t r0, r1, r2, r3;
            ldm4(r0, r1, r2, r3, wsA + rn * 128 + ((chunk ^ (rn & 7)) << 4));
            bb[pr * 2][0] = r0; bb[pr * 2 + 1][0] = r1;
            bb[pr * 2][1] = r2; bb[pr * 2 + 1][1] = r3;
        }
#pragma unroll
        for (int mt = 0; mt < 2; mt++)
#pragma unroll
            for (int nt = 0; nt < 4; nt++) mma16816(acc[mt][nt], a[mt], bb[nt]);
    }
    int g = lane >> 2, t4 = lane & 3;
#pragma unroll
    for (int mt = 0; mt < 2; mt++)
#pragma unroll
        for (int nt = 0; nt < 4; nt++)
#pragma unroll
            for (int h2 = 0; h2 < 2; h2++) {
                int row = wm * 32 + mt * 16 + g + h2 * 8;
                int col = wn * 32 + nt * 8 + t4 * 2;
                zs[(size_t)col * 136 + row]       = __float2half(acc[mt][nt][h2 * 2]);
                zs[(size_t)(col + 1) * 136 + row] = __float2half(acc[mt][nt][h2 * 2 + 1]);
            }
}

// z tiled-layout store: v packs (m, m+1) halves for dim d
__device__ __forceinline__ void store_z_tiled(__half* zbase, int b, int d, int m,
                                              uint32_t v) {
    int kc = m >> 6, ml = m & 63, c = ml >> 3;
    size_t off = ((size_t)(b * 64 + kc)) * 8192 + d * 128 + ((c ^ (d & 7)) << 4) + (ml & 7) * 2;
    *reinterpret_cast<uint32_t*>(reinterpret_cast<char*>(zbase) + off) = v;
}

// ---------------- 1) deg + dis + fp16 tiled/swizzled conversion -------------
__global__ void conv_deg(const float* __restrict__ adj) {
    size_t row = blockIdx.x;                    // global node b*NN+m
    int t = threadIdx.x;
    const float4* p = reinterpret_cast<const float4*>(adj + row * NN);
    float4 v[8];
#pragma unroll
    for (int i = 0; i < 8; i++) v[i] = p[t + i * 128];
    float s = 0.f;
#pragma unroll
    for (int i = 0; i < 8; i++) s += (v[i].x + v[i].y) + (v[i].z + v[i].w);
#pragma unroll
    for (int o = 16; o; o >>= 1) s += __shfl_xor_sync(0xffffffffu, s, o);
    __shared__ float ws[4];
    __shared__ float sdis;
    if ((t & 31) == 0) ws[t >> 5] = s;
    __syncthreads();
    if (t == 0) {
        float tot = ws[0] + ws[1] + ws[2] + ws[3];
        float dis = rsqrtf(fmaxf(tot, 1.0f));
        g_dis[row] = dis;
        sdis = dis;
    }
    __syncthreads();
    float d = sdis;
    int bidx = (int)(row >> 12), m = (int)(row & 4095);
    int mt = m >> 7, r = m & 127;
    char* blockBase = reinterpret_cast<char*>(g_adjh) +
                      ((size_t)(bidx * 32 + mt)) * 64 * 16384;
#pragma unroll
    for (int i = 0; i < 8; i++) {
        __half2 lo = __floats2half2_rn(v[i].x * d, v[i].y * d);
        __half2 hi = __floats2half2_rn(v[i].z * d, v[i].w * d);
        uint2 o;
        o.x = *reinterpret_cast<uint32_t*>(&lo);
        o.y = *reinterpret_cast<uint32_t*>(&hi);
        int k0 = 4 * (t + i * 128);
        int kc = k0 >> 6, c = (k0 & 63) >> 3;
        size_t off = (size_t)kc * 16384 + r * 128 + ((c ^ (r & 7)) << 4) + (k0 & 7) * 2;
        *reinterpret_cast<uint2*>(blockBase + off) = o;
    }
}

// ---------------- 2) proj1: z1 = dis*(x @ W1), fp16, tiled layout -----------
__global__ void __launch_bounds__(256) proj1_kernel(
    const int* __restrict__ ntypes, const int* __restrict__ nlabels,
    const float* __restrict__ te, const float* __restrict__ le,
    const float* __restrict__ W1) {
    __shared__ __align__(16) char sm[41984];   // xs 16K | ws 8K | zs 17408
    int tid = threadIdx.x;
    int base = blockIdx.x * 128;
    load_wT(W1, sm + 16384, tid);

    int node_l = tid >> 1, half = tid & 1;
    int node = base + node_l;
    const float* src = half ? (le + nlabels[node] * 32) : (te + ntypes[node] * 32);
    float dv = g_dis[node];
#pragma unroll
    for (int j = 0; j < 8; j++) {
        float4 v = reinterpret_cast<const float4*>(src)[j];
        __half2 p0 = __floats2half2_rn(v.x * dv, v.y * dv);
        __half2 p1 = __floats2half2_rn(v.z * dv, v.w * dv);
        int col = half * 32 + j * 4;
        int chunk = col >> 3;
        int off = node_l * 128 + ((chunk ^ (node_l & 7)) << 4) + (col & 7) * 2;
        uint2 u;
        u.x = *reinterpret_cast<uint32_t*>(&p0);
        u.y = *reinterpret_cast<uint32_t*>(&p1);
        *reinterpret_cast<uint2*>(sm + off) = u;
    }
    __syncthreads();

    int warp = tid >> 5, lane = tid & 31, wm = warp >> 1, wn = warp & 1;
    uint32_t sA = (uint32_t)__cvta_generic_to_shared(sm);
    __half* zs = reinterpret_cast<__half*>(sm + 24576);
    mini_mma_store(sA, sA + 16384, zs, wm, wn, lane);
    __syncthreads();

    int b = base >> 12, m0 = base & 4095;
    for (int idx = tid; idx < 4096; idx += 256) {
        int d = idx >> 6, cw = idx & 63;
        uint32_t v = *reinterpret_cast<uint32_t*>(zs + d * 136 + cw * 2);
        store_z_tiled(g_z1, b, d, m0 + cw * 2, v);
    }
}

// ---------------- 3) main GEMM (bulk-copy 2-stage, 4 CTAs/SM, single wave) --
// mode 1: acc = adjh @ z1^T ; h = relu(acc + b1); z2 = dis[m]*(h @ W2) -> g_z2
// mode 2: acc = adjh @ z2^T ; h = relu(acc + b2); pool partials -> g_pool
// smem: A stages [2][16KB] @0 | B stages [2][8KB] @32768 ; total 49152 dynamic
__global__ void __launch_bounds__(256, 4) gcn_gemm(
    const float* __restrict__ bias, const float* __restrict__ Wnext, int mode) {
    extern __shared__ char sm[];
    __shared__ __align__(8) uint64_t mb_full[2];
    int tid = threadIdx.x, b = blockIdx.y, m0 = blockIdx.x * 128;
    uint32_t sA = (uint32_t)__cvta_generic_to_shared(sm);
    uint32_t sB = sA + 32768;
    uint32_t mbF = (uint32_t)__cvta_generic_to_shared(mb_full);
    int warp = tid >> 5, lane = tid & 31, wm = warp >> 1, wn = warp & 1;
    int g = lane >> 2, t4 = lane & 3;

    const char* aTile = reinterpret_cast<const char*>(g_adjh) +
                        ((size_t)(b * 32 + blockIdx.x)) * 64 * 16384;
    const char* zTile = reinterpret_cast<const char*>(mode == 1 ? g_z1 : g_z2) +
                        (size_t)b * 64 * 8192;

    if (tid == 0) {
        mbar_init(mbF + 0, 1);
        mbar_init(mbF + 8, 1);
    }
    __syncthreads();
    if (tid == 0) {
#pragma unroll
        for (int s = 0; s < 2; s++) {
            mbar_expect(mbF + s * 8, 24576);
            bulk_g2s_stream(sA + s * 16384, aTile + (size_t)s * 16384, 16384, mbF + s * 8);
            bulk_g2s(sB + s * 8192,  zTile + (size_t)s * 8192,  8192,  mbF + s * 8);
        }
    }

    float acc[2][4][4];
#pragma unroll
    for (int mt = 0; mt < 2; mt++)
#pragma unroll
        for (int nt = 0; nt < 4; nt++)
#pragma unroll
            for (int c = 0; c < 4; c++) acc[mt][nt][c] = 0.f;

    for (int kb = 0; kb < 64; kb++) {
        int buf = kb & 1;
        uint32_t par = (kb >> 1) & 1;
        mbar_wait(mbF + buf * 8, par);
        uint32_t Ab = sA + buf * 16384, Bb = sB + buf * 8192;
#pragma unroll
        for (int kt = 0; kt < 4; kt++) {
            uint32_t a[2][4], bb[4][2];
            int chunk = kt * 2 + (lane >> 4);
#pragma unroll
            for (int mt = 0; mt < 2; mt++) {
                int row = wm * 32 + mt * 16 + (lane & 15);
                ldm4(a[mt][0], a[mt][1], a[mt][2], a[mt][3],
                     Ab + row * 128 + ((chunk ^ (row & 7)) << 4));
            }
#pragma unroll
            for (int pr = 0; pr < 2; pr++) {
                int rn = wn * 32 + pr * 16 + (lane & 15);
                uint32_t r0, r1, r2, r3;
                ldm4(r0, r1, r2, r3, Bb + rn * 128 + ((chunk ^ (rn & 7)) << 4));
                bb[pr * 2][0] = r0; bb[pr * 2 + 1][0] = r1;
                bb[pr * 2][1] = r2; bb[pr * 2 + 1][1] = r3;
            }
#pragma unroll
            for (int mt = 0; mt < 2; mt++)
#pragma unroll
                for (int nt = 0; nt < 4; nt++) mma16816(acc[mt][nt], a[mt], bb[nt]);
        }
        __syncthreads();
        if (tid == 0 && kb + 2 < 64) {
            mbar_expect(mbF + buf * 8, 24576);
            bulk_g2s_stream(sA + buf * 16384, aTile + (size_t)(kb + 2) * 16384, 16384, mbF + buf * 8);
            bulk_g2s(sB + buf * 8192,  zTile + (size_t)(kb + 2) * 8192,  8192,  mbF + buf * 8);
        }
    }

    if (mode == 1) {
        // W^T into smem tail + stage h' fp16 tile at sm[0]; zs at sm+16384
        load_wT(Wnext, sm + 40960, tid);
#pragma unroll
        for (int mt = 0; mt < 2; mt++)
#pragma unroll
            for (int h2 = 0; h2 < 2; h2++) {
                int row = wm * 32 + mt * 16 + g + h2 * 8;
                float dv = g_dis[b * NN + m0 + row];
#pragma unroll
                for (int nt = 0; nt < 4; nt++) {
                    int col = wn * 32 + nt * 8 + t4 * 2;
                    float v0 = fmaxf(acc[mt][nt][h2 * 2]     + bias[col],     0.f) * dv;
                    float v1 = fmaxf(acc[mt][nt][h2 * 2 + 1] + bias[col + 1], 0.f) * dv;
                    int chunk = col >> 3;
                    int off = row * 128 + ((chunk ^ (row & 7)) << 4) + (col & 7) * 2;
                    __half2 p = __floats2half2_rn(v0, v1);
                    *reinterpret_cast<uint32_t*>(sm + off) = *reinterpret_cast<uint32_t*>(&p);
                }
            }
        __syncthreads();
        __half* zs = reinterpret_cast<__half*>(sm + 16384);
        mini_mma_store(sA, sA + 40960, zs, wm, wn, lane);
        __syncthreads();
        for (int idx = tid; idx < 4096; idx += 256) {
            int d = idx >> 6, cw = idx & 63;
            uint32_t v = *reinterpret_cast<uint32_t*>(zs + d * 136 + cw * 2);
            store_z_tiled(g_z2, b, d, m0 + cw * 2, v);
        }
    } else {
        // stage h = relu(acc + b2) fp32, then pool partials
        float* hs = reinterpret_cast<float*>(sm);
#pragma unroll
        for (int mt = 0; mt < 2; mt++)
#pragma unroll
            for (int h2 = 0; h2 < 2; h2++) {
                int row = wm * 32 + mt * 16 + g + h2 * 8;
#pragma unroll
                for (int nt = 0; nt < 4; nt++) {
                    int col = wn * 32 + nt * 8 + t4 * 2;
                    hs[row * 65 + col]     = fmaxf(acc[mt][nt][h2 * 2]     + bias[col],     0.f);
                    hs[row * 65 + col + 1] = fmaxf(acc[mt][nt][h2 * 2 + 1] + bias[col + 1], 0.f);
                }
            }
        __syncthreads();
        float* red = reinterpret_cast<float*>(sm + 33792);
        int d = tid & 63, part = tid >> 6;
        float s = 0.f, mx = -1e30f;
#pragma unroll 4
        for (int r = part * 32; r < part * 32 + 32; r++) {
            float v = hs[r * 65 + d];
            s += v; mx = fmaxf(mx, v);
        }
        red[tid] = s; red[256 + tid] = mx;
        __syncthreads();
        if (tid < 64) {
            float S = red[tid] + red[tid + 64] + red[tid + 128] + red[tid + 192];
            float M = fmaxf(fmaxf(red[256 + tid], red[256 + tid + 64]),
                            fmaxf(red[256 + tid + 128], red[256 + tid + 192]));
            g_pool[((b * 32 + blockIdx.x) << 7) + tid]      = S;
            g_pool[((b * 32 + blockIdx.x) << 7) + 64 + tid] = M;
        }
    }
}

// ---------------- 4) final combine + readout (parallelized) ------------------
__global__ void __launch_bounds__(256) final_kernel(
    const float* __restrict__ Wr, const float* __restrict__ br,
    float* __restrict__ out) {
    int b = blockIdx.x, t = threadIdx.x;       // 256 threads
    __shared__ float part[256];
    __shared__ float pooled[128];
    int p = t & 127, h = t >> 7;
    bool isSum = p < 64;
    float a = isSum ? 0.f : -1e30f;
#pragma unroll
    for (int c = h; c < 32; c += 2) {
        float v = g_pool[((b * 32 + c) << 7) + p];
        a = isSum ? (a + v) : fmaxf(a, v);
    }
    part[t] = a;
    __syncthreads();
    if (t < 128) {
        float x = part[t], y = part[t + 128];
        pooled[t] = (t < 64) ? (x + y) * (1.0f / 4096.0f) : fmaxf(x, y);
    }
    __syncthreads();
    int o = t >> 2, q = t & 3;
    float s = 0.f;
#pragma unroll
    for (int j = q * 32; j < q * 32 + 32; j++) s += pooled[j] * Wr[o * 128 + j];
    s += __shfl_xor_sync(0xffffffffu, s, 1);
    s += __shfl_xor_sync(0xffffffffu, s, 2);
    if (q == 0) out[b * 64 + o] = s + br[o];
}

// ---------------- launch -----------------------------------------------------
extern "C" void kernel_launch(void* const* d_in, const int* in_sizes, int n_in,
                              void* d_out, int out_size) {
    const int*   node_types  = (const int*)  d_in[0];
    const int*   node_labels = (const int*)  d_in[1];
    const float* adj         = (const float*)d_in[2];
    const float* type_emb    = (const float*)d_in[3];
    const float* label_emb   = (const float*)d_in[4];
    const float* W1          = (const float*)d_in[5];
    const float* b1          = (const float*)d_in[6];
    const float* W2          = (const float*)d_in[7];
    const float* b2          = (const float*)d_in[8];
    const float* Wr          = (const float*)d_in[9];
    const float* br          = (const float*)d_in[10];
    float* out = (float*)d_out;

    cudaFuncSetAttribute(gcn_gemm, cudaFuncAttributeMaxDynamicSharedMemorySize, 49152);

    conv_deg<<<BB * NN, 128>>>(adj);
    proj1_kernel<<<BB * NN / 128, 256>>>(node_types, node_labels, type_emb, label_emb, W1);
    gcn_gemm<<<dim3(32, BB), 256, 49152>>>(b1, W2, 1);
    gcn_gemm<<<dim3(32, BB), 256, 49152>>>(b2, nullptr, 2);
    final_kernel<<<BB, 256>>>(Wr, br, out);
}